// round 3
// baseline (speedup 1.0000x reference)
#include <cuda_runtime.h>
#include <cstddef>

#define NE     80000
#define NN     8000
#define CC     128
#define HID    128
#define M0     7
#define FULLC  49
#define MALL   29
#define OUT2   896
#define LN_EPS 1e-5f
#define INV_RESCALE (1.0f / 23.395f)

// ---------------- scratch (__device__ globals: allocation-free) ----------------
__device__ float g_h[(size_t)NE * HID];     // 41 MB  : post-activation hidden
__device__ float g_rad[(size_t)NE * OUT2];  // 287 MB : per-edge radial [E][7][128]
__device__ int   g_counts[NN];
__device__ int   g_offsets[NN + 1];
__device__ int   g_cursor[NN];
__device__ int   g_eids[NE];

// ---------------- CSR build ----------------
__global__ void k_zero()
{
    int i = blockIdx.x * blockDim.x + threadIdx.x;
    if (i < NN) { g_counts[i] = 0; g_cursor[i] = 0; }
}

// NOTE: edge_index is int32 on device (JAX x64-disabled silently downcasts int64).
__global__ void k_count(const int* __restrict__ ei)
{
    int e = blockIdx.x * blockDim.x + threadIdx.x;
    if (e < NE) {
        int d = ei[NE + e];
        atomicAdd(&g_counts[d], 1);
    }
}

// single-block exclusive scan over g_counts -> g_offsets (8000 elems, 8 passes)
__global__ void k_scan()
{
    __shared__ int s[1024];
    int carry = 0;
    for (int base = 0; base < NN; base += 1024) {
        int i = base + threadIdx.x;
        int v = (i < NN) ? g_counts[i] : 0;
        s[threadIdx.x] = v;
        __syncthreads();
        for (int off = 1; off < 1024; off <<= 1) {
            int t = (threadIdx.x >= off) ? s[threadIdx.x - off] : 0;
            __syncthreads();
            s[threadIdx.x] += t;
            __syncthreads();
        }
        if (i < NN) g_offsets[i] = carry + s[threadIdx.x] - v;  // exclusive
        int tot = s[1023];
        __syncthreads();
        carry += tot;
    }
    if (threadIdx.x == 0) g_offsets[NN] = carry;
}

__global__ void k_scatter(const int* __restrict__ ei)
{
    int e = blockIdx.x * blockDim.x + threadIdx.x;
    if (e < NE) {
        int d = ei[NE + e];
        int p = atomicAdd(&g_cursor[d], 1);
        g_eids[g_offsets[d] + p] = e;
    }
}

// ---------------- tiled fp32 GEMM: C = A[M,K] @ B[K,N] + bias[N] ----------------
// 64x64 block tile, K-chunk 16, 256 threads, 4x4 register microtile.
__global__ __launch_bounds__(256) void k_gemm(
    const float* __restrict__ A, const float* __restrict__ B,
    const float* __restrict__ bias, float* __restrict__ C,
    int M, int N, int K)
{
    __shared__ float As[16][64];
    __shared__ float Bs[16][64];
    const int tid = threadIdx.x;
    const int m0 = blockIdx.y * 64;
    const int n0 = blockIdx.x * 64;
    const int ty = tid >> 4, tx = tid & 15;
    const int lm = tid >> 2;            // A load: row within tile (0..63)
    const int lk = (tid & 3) * 4;       // A load: kk base {0,4,8,12}
    const int bn = (tid & 15) * 4;      // B load: col within tile
    const int bk = tid >> 4;            // B load: kk (0..15)

    float acc[4][4];
#pragma unroll
    for (int i = 0; i < 4; i++)
#pragma unroll
        for (int j = 0; j < 4; j++) acc[i][j] = 0.f;

    for (int k0 = 0; k0 < K; k0 += 16) {
        float4 a4 = *reinterpret_cast<const float4*>(A + (size_t)(m0 + lm) * K + k0 + lk);
        As[lk + 0][lm] = a4.x;
        As[lk + 1][lm] = a4.y;
        As[lk + 2][lm] = a4.z;
        As[lk + 3][lm] = a4.w;
        *reinterpret_cast<float4*>(&Bs[bk][bn]) =
            *reinterpret_cast<const float4*>(B + (size_t)(k0 + bk) * N + n0 + bn);
        __syncthreads();
#pragma unroll
        for (int kk = 0; kk < 16; kk++) {
            float a[4], b[4];
            *reinterpret_cast<float4*>(a) = *reinterpret_cast<const float4*>(&As[kk][ty * 4]);
            *reinterpret_cast<float4*>(b) = *reinterpret_cast<const float4*>(&Bs[kk][tx * 4]);
#pragma unroll
            for (int i = 0; i < 4; i++)
#pragma unroll
                for (int j = 0; j < 4; j++) acc[i][j] += a[i] * b[j];
        }
        __syncthreads();
    }

    float bb[4];
#pragma unroll
    for (int j = 0; j < 4; j++) bb[j] = bias[n0 + tx * 4 + j];
#pragma unroll
    for (int i = 0; i < 4; i++) {
        float4 o;
        o.x = acc[i][0] + bb[0];
        o.y = acc[i][1] + bb[1];
        o.z = acc[i][2] + bb[2];
        o.w = acc[i][3] + bb[3];
        *reinterpret_cast<float4*>(C + (size_t)(m0 + ty * 4 + i) * N + n0 + tx * 4) = o;
    }
}

// ---------------- LayerNorm + SiLU (in place on g_h), one warp per edge ----------------
__global__ void k_ln(const float* __restrict__ g1, const float* __restrict__ be1)
{
    int e = blockIdx.x * blockDim.y + threadIdx.y;
    if (e >= NE) return;
    int lane = threadIdx.x;
    float* hp = g_h + (size_t)e * HID;
    float4 v = reinterpret_cast<float4*>(hp)[lane];
    float s  = v.x + v.y + v.z + v.w;
    float ss = v.x * v.x + v.y * v.y + v.z * v.z + v.w * v.w;
#pragma unroll
    for (int o = 16; o > 0; o >>= 1) {
        s  += __shfl_xor_sync(0xffffffffu, s, o);
        ss += __shfl_xor_sync(0xffffffffu, ss, o);
    }
    float mu  = s * (1.0f / HID);
    float var = ss * (1.0f / HID) - mu * mu;
    float rs  = rsqrtf(var + LN_EPS);
    float4 g  = reinterpret_cast<const float4*>(g1)[lane];
    float4 be = reinterpret_cast<const float4*>(be1)[lane];
    float4 o;
    o.x = (v.x - mu) * rs * g.x + be.x;
    o.y = (v.y - mu) * rs * g.y + be.y;
    o.z = (v.z - mu) * rs * g.z + be.z;
    o.w = (v.w - mu) * rs * g.w + be.w;
    o.x = o.x / (1.0f + __expf(-o.x));
    o.y = o.y / (1.0f + __expf(-o.y));
    o.z = o.z / (1.0f + __expf(-o.z));
    o.w = o.w / (1.0f + __expf(-o.w));
    reinterpret_cast<float4*>(hp)[lane] = o;
}

// ---------------- per-node combine: out[n] = x[n] + sum_e wig_e[49,7] @ rad_e[7,128] / R ----
// one block per node, thread = channel c, 49 fp32 accumulators in registers, no atomics.
__global__ __launch_bounds__(128) void k_combine(
    const float* __restrict__ x, const float* __restrict__ wig,
    float* __restrict__ out)
{
    const int n = blockIdx.x;
    const int c = threadIdx.x;
    __shared__ float ws[FULLC * M0];

    float acc[FULLC];
#pragma unroll
    for (int f = 0; f < FULLC; f++) acc[f] = 0.f;

    const int beg = g_offsets[n];
    const int end = g_offsets[n + 1];
    for (int t = beg; t < end; t++) {
        const int e = g_eids[t];
        __syncthreads();  // protect ws reuse from previous edge
        const float* we = wig + (size_t)e * (FULLC * MALL);
        for (int i = c; i < FULLC * M0; i += 128) {
            int f = i / M0;
            int m = i - f * M0;
            ws[i] = we[f * MALL + m] * INV_RESCALE;
        }
        __syncthreads();
        const float* re = g_rad + (size_t)e * OUT2 + c;
        float r[M0];
#pragma unroll
        for (int m = 0; m < M0; m++) r[m] = re[m * CC];
#pragma unroll
        for (int f = 0; f < FULLC; f++) {
            float sfm = acc[f];
#pragma unroll
            for (int m = 0; m < M0; m++) sfm += ws[f * M0 + m] * r[m];
            acc[f] = sfm;
        }
    }

    const float* xb = x + (size_t)n * (FULLC * CC) + c;
    float* ob = out + (size_t)n * (FULLC * CC) + c;
#pragma unroll
    for (int f = 0; f < FULLC; f++) ob[f * CC] = xb[f * CC] + acc[f];
}

// ---------------- launch ----------------
extern "C" void kernel_launch(void* const* d_in, const int* in_sizes, int n_in,
                              void* d_out, int out_size)
{
    const float* x      = (const float*)d_in[0];
    const float* x_edge = (const float*)d_in[1];
    const float* wig    = (const float*)d_in[2];
    const float* W1     = (const float*)d_in[3];
    const float* b1     = (const float*)d_in[4];
    const float* g1     = (const float*)d_in[5];
    const float* be1    = (const float*)d_in[6];
    const float* W2     = (const float*)d_in[7];
    const float* b2     = (const float*)d_in[8];
    const int*   ei     = (const int*)d_in[9];   // int32: JAX x64-disabled downcast
    float* out          = (float*)d_out;

    float* p_h   = nullptr;
    float* p_rad = nullptr;
    cudaGetSymbolAddress((void**)&p_h, g_h);
    cudaGetSymbolAddress((void**)&p_rad, g_rad);

    // CSR build (cheap)
    k_zero<<<(NN + 255) / 256, 256>>>();
    k_count<<<(NE + 255) / 256, 256>>>(ei);
    k_scan<<<1, 1024>>>();
    k_scatter<<<(NE + 255) / 256, 256>>>(ei);

    // radial MLP: GEMM1 -> LN+SiLU -> GEMM2
    k_gemm<<<dim3(HID / 64, NE / 64), 256>>>(x_edge, W1, b1, p_h, NE, HID, HID);
    k_ln<<<NE / 8, dim3(32, 8)>>>(g1, be1);
    k_gemm<<<dim3(OUT2 / 64, NE / 64), 256>>>(p_h, W2, b2, p_rad, NE, OUT2, HID);

    // per-node wigner contraction + residual, no atomics
    k_combine<<<NN, 128>>>(x, wig, out);
}